// round 16
// baseline (speedup 1.0000x reference)
#include <cuda_runtime.h>
#include <cuda_fp16.h>
#include <math.h>
#include <stdint.h>

// Problem constants
#define Bb   64
#define Nn   64
#define Hh   128
#define NBb  8
#define Tt   32
#define Ll   2
#define HSZ  (Bb*Nn*Hh)
#define VSZ  (Bb*Nn*3*Hh)
#define NITEMS (Bb*16)      // 1024 work items (b, jg)
#define MSG_GRID 456        // 152 SMs x 3 CTAs

// ---------------- device scratch (no allocations allowed) ----------------
__device__ float    g_h   [2*HSZ];         // node scalar features (ping-pong)
__device__ float    g_v   [2*VSZ];         // vector features SoA (ping-pong)
__device__ uint32_t g_aF  [Bb*16*1024];    // aggregates, fp16 A-frag layout per (b,jg)
__device__ uint32_t g_Wr2H[Ll*8192];       // Wr2^T fp16 B-frags [kb8][c128][8w]
__device__ uint32_t g_WuH [Ll*8192];       // Wupd^T fp16 B-frags
__device__ uint32_t g_WmH [Ll*8192];       // Wmix^T fp16 B-frags
__device__ uint32_t g_Wg1H[8192];          // Wg1^T fp16 B-frags
__device__ uint32_t g_Wg2H[8192];          // Wg2^T fp16 B-frags
__device__ int      g_wc  [Ll];            // work-steal counters (reset in setup)

// ---------------- helpers -------------------------------------------------
__device__ __forceinline__ void mma_f16(float* c,
                                        uint32_t a0, uint32_t a1, uint32_t a2, uint32_t a3,
                                        uint32_t b0, uint32_t b1) {
    asm volatile(
        "mma.sync.aligned.m16n8k16.row.col.f32.f16.f16.f32 "
        "{%0,%1,%2,%3},{%4,%5,%6,%7},{%8,%9},{%0,%1,%2,%3};"
        : "+f"(c[0]), "+f"(c[1]), "+f"(c[2]), "+f"(c[3])
        : "r"(a0), "r"(a1), "r"(a2), "r"(a3), "r"(b0), "r"(b1));
}
__device__ __forceinline__ float tanh_approx(float x) {
    float r;
    asm("tanh.approx.f32 %0, %1;" : "=f"(r) : "f"(x));
    return r;
}
// silu(x) = 0.5x + 0.5x * tanh(0.5x)
__device__ __forceinline__ float silu_f(float x) {
    float s = 0.5f * x;
    return fmaf(s, tanh_approx(s), s);
}
__device__ __forceinline__ uint32_t pack_h2(float lo, float hi) {
    __half2 h = __floats2half2_rn(lo, hi);
    return *(uint32_t*)&h;
}

// ---------------- K1: fused setup (z-probe + init + weight frags) ---------
__global__ __launch_bounds__(256, 2)
void setup_kernel(const int* __restrict__ z,
                  const float* __restrict__ gf,
                  const float* __restrict__ emb,
                  const float* __restrict__ Wt,
                  const float* __restrict__ Wr2,
                  const float* __restrict__ Wupd,
                  const float* __restrict__ Wmix,
                  const float* __restrict__ Wg1,
                  const float* __restrict__ Wg2) {
    const int blk = blockIdx.x;
    const int tid = threadIdx.x;
    if (blk == 0 && tid == 0) { g_wc[0] = 0; g_wc[1] = 0; }
    if (blk < 512) {
        // ---- init into buffer 0: h = emb[z] + t @ Wt ; v = 0 ----
        int t32 = tid & 31;
        int v = z[2*t32 + 1] | z[2*(t32 + 32) + 1];
        int nz = __reduce_or_sync(0xffffffffu, v);
        const int z64 = (nz == 0);
        const int n0 = blk * 8;
        const int b  = n0 >> 6;
        const int c  = tid & 127;
        const int qt = tid >> 7;
        float tw = 0.f;
        const float* g = gf + b*Tt;
        #pragma unroll
        for (int t = 0; t < Tt; ++t) tw += g[t] * Wt[t*Hh + c];
        #pragma unroll
        for (int m = 0; m < 4; ++m) {
            const int n  = n0 + qt*4 + m;
            const int zi = z64 ? z[2*n] : z[n];
            g_h[n*Hh + c] = emb[zi*Hh + c] + tw;
            g_v[(n*3 + 0)*Hh + c] = 0.f;
            g_v[(n*3 + 1)*Hh + c] = 0.f;
            g_v[(n*3 + 2)*Hh + c] = 0.f;
        }
    } else {
        // ---- weight -> fp16 B-fragment layout ----
        const int b2 = blk - 512;
        const float* src;
        uint32_t*    dst;
        if (b2 < 3*Ll) {
            const int a = b2 / Ll;
            const int l = b2 % Ll;
            src = ((a == 0) ? Wr2 : (a == 1) ? Wupd : Wmix) + l*Hh*Hh;
            dst = ((a == 0) ? g_Wr2H : (a == 1) ? g_WuH : g_WmH) + l*8192;
        } else if (b2 == 3*Ll) {
            src = Wg1; dst = g_Wg1H;
        } else {
            src = Wg2; dst = g_Wg2H;
        }
        for (int idx = tid; idx < 8192; idx += 256) {
            int c  = idx >> 6, kp = idx & 63;
            int k  = kp * 2;
            int kb = k >> 4;
            int kw = k & 15;
            int q  = (kw >> 1) & 3;
            int hi = kw >> 3;
            dst[(kb*128 + c)*8 + q*2 + hi] = pack_h2(src[k*Hh + c], src[(k+1)*Hh + c]);
        }
    }
}

// ---------------- smem word offsets for msg kernel ------------------------
#define OFF_W2T  0          // 8192 words: fp16 B frags [kb8][c128][8w]
#define OFF_S    8192       // 8192:  fp16 A frags 2 receivers [kb8][mtS8][r16][8w]
#define OFF_RBF  16384      // 1024:  fp16 rb [jl4][i64][4w]
#define OFF_U4F  17408      // 1024:  [jl4][i64] float4
#define MSG_WORDS 18432     // 73728 bytes -> 3 CTAs/SM

// ---------------- K2: persistent message pass + fused update --------------
// 456 CTAs, work-steal over 1024 (b, jg) items. W2T staged once per CTA.
__global__ __launch_bounds__(256, 3)
void msg_kernel(const float* __restrict__ pos,
                const float* __restrict__ Wr1,
                int layer) {
    extern __shared__ float smf[];
    uint32_t* W2Tf = (uint32_t*)smf + OFF_W2T;
    uint32_t* Sf   = (uint32_t*)smf + OFF_S;
    uint32_t* rbf  = (uint32_t*)smf + OFF_RBF;
    float*    u4f  = smf + OFF_U4F;
    __shared__ int s_item;

    const float* h_in  = g_h + (layer & 1)*HSZ;
    float*       h_out = g_h + ((layer + 1) & 1)*HSZ;
    const float* v_in  = g_v + (layer & 1)*VSZ;
    float*       v_out = g_v + ((layer + 1) & 1)*VSZ;

    const int tid  = threadIdx.x;
    const int lane = tid & 31;
    const int widh = tid >> 5;              // 0..7
    const int r4   = lane >> 2;             // 0..7
    const int q4   = lane & 3;              // 0..3

    // ---- one-time staging: W2T fp16 fragments, Wr1 B-frags ----
    for (int idx = tid; idx < 8192; idx += 256) W2Tf[idx] = g_Wr2H[layer*8192 + idx];
    uint32_t wbA, wbB;
    {
        int cA = widh*16 + r4;
        int cB = cA + 8;
        wbA = pack_h2(Wr1[(q4*2)*Hh + cA], Wr1[(q4*2+1)*Hh + cA]);
        wbB = pack_h2(Wr1[(q4*2)*Hh + cB], Wr1[(q4*2+1)*Hh + cB]);
    }

    const float PI5 = 0.62831853071795864769f;   // pi/5
    const float s63 = 1.0f / 63.0f;

    while (true) {
        __syncthreads();                       // prior item fully done
        if (tid == 0) s_item = atomicAdd(&g_wc[layer], 1);
        __syncthreads();
        const int item = s_item;
        if (item >= NITEMS) return;
        const int b  = item >> 4;
        const int jg = item & 15;

        // ---- register-cache h for this batch: 8 rows x 2 float2 ----
        float2 hreg[4][2][2];
        {
            const float* hb = h_in + (size_t)b*Nn*Hh;
            #pragma unroll
            for (int mt = 0; mt < 4; ++mt)
                #pragma unroll
                for (int rg = 0; rg < 2; ++rg) {
                    int i = mt*16 + r4 + rg*8;
                    #pragma unroll
                    for (int nt = 0; nt < 2; ++nt) {
                        int c = widh*16 + nt*8 + q4*2;
                        hreg[mt][rg][nt] = *(const float2*)(hb + i*Hh + c);
                    }
                }
        }

        // ---- geometry + bessel for 4 receivers (256 = 4j x 64i) ----
        {
            const int jl = tid >> 6;             // 0..3
            const int i  = tid & 63;
            const int j  = jg*4 + jl;
            const float* pb = pos + b*Nn*3;
            float dx = pb[j*3+0] - pb[i*3+0];
            float dy = pb[j*3+1] - pb[i*3+1];
            float dz = pb[j*3+2] - pb[i*3+2];
            float r2 = dx*dx + dy*dy + dz*dz + 1e-12f;
            float r  = sqrtf(r2);
            float inv = 1.0f / r;
            ((float4*)u4f)[jl*Nn + i] = make_float4(dx*inv, dy*inv, dz*inv, 0.f);
            float fc = 0.0f;
            if (r < 5.0f && i != j) fc = 0.5f * (__cosf(PI5 * r) + 1.0f);
            float sc  = inv * fc;
            float arg = PI5 * r;
            float rv[8];
            #pragma unroll
            for (int q = 0; q < NBb; ++q) rv[q] = __sinf((float)(q+1) * arg) * sc;
            uint4 rw;
            rw.x = pack_h2(rv[0], rv[1]);
            rw.y = pack_h2(rv[2], rv[3]);
            rw.z = pack_h2(rv[4], rv[5]);
            rw.w = pack_h2(rv[6], rv[7]);
            ((uint4*)rbf)[jl*Nn + i] = rw;
        }
        __syncthreads();

        for (int rr = 0; rr < 2; ++rr) {
            // ---- S = silu(rb @ Wr1) for receivers rr*2, rr*2+1 ----
            #pragma unroll
            for (int jh = 0; jh < 2; ++jh) {
                const uint32_t* rbj = rbf + (rr*2 + jh)*Nn*4;
                #pragma unroll
                for (int mt = 0; mt < 4; ++mt) {
                    int r0 = mt*16 + r4;
                    uint32_t A0 = rbj[r0*4 + q4];
                    uint32_t A1 = rbj[(r0+8)*4 + q4];
                    float s0[4] = {0.f, 0.f, 0.f, 0.f};
                    float s1[4] = {0.f, 0.f, 0.f, 0.f};
                    mma_f16(s0, A0, A1, 0u, 0u, wbA, 0u);
                    mma_f16(s1, A0, A1, 0u, 0u, wbB, 0u);
                    const int mtS = jh*4 + mt;
                    uint32_t* Sb = Sf + (widh*8 + mtS)*128 + r4*8 + q4*2;
                    *(uint2*)(Sb)      = make_uint2(pack_h2(silu_f(s0[0]), silu_f(s0[1])),
                                                    pack_h2(silu_f(s1[0]), silu_f(s1[1])));
                    *(uint2*)(Sb + 64) = make_uint2(pack_h2(silu_f(s0[2]), silu_f(s0[3])),
                                                    pack_h2(silu_f(s1[2]), silu_f(s1[3])));
                }
            }
            __syncthreads();

            // ---- per receiver: kb-outer GEMM + epilogue ----
            #pragma unroll
            for (int jh = 0; jh < 2; ++jh) {
                float acc[4][2][4];
                #pragma unroll
                for (int mt = 0; mt < 4; ++mt)
                    #pragma unroll
                    for (int nt = 0; nt < 2; ++nt) {
                        acc[mt][nt][0]=0.f; acc[mt][nt][1]=0.f; acc[mt][nt][2]=0.f; acc[mt][nt][3]=0.f;
                    }
                const uint32_t* Bp = W2Tf + (widh*16 + r4)*8 + q4*2;
                const uint32_t* Am0 = Sf + jh*4*128 + r4*8 + q4*2;

                #pragma unroll
                for (int kb = 0; kb < 8; ++kb) {
                    uint2 Bv0 = *(const uint2*)(Bp + kb*1024);
                    uint2 Bv1 = *(const uint2*)(Bp + kb*1024 + 64);
                    #pragma unroll
                    for (int mt = 0; mt < 4; ++mt) {
                        const uint32_t* Am = Am0 + kb*1024 + mt*128;
                        uint2 A0 = *(const uint2*)(Am);
                        uint2 A1 = *(const uint2*)(Am + 64);
                        mma_f16(acc[mt][0], A0.x, A1.x, A0.y, A1.y, Bv0.x, Bv0.y);
                        mma_f16(acc[mt][1], A0.x, A1.x, A0.y, A1.y, Bv1.x, Bv1.y);
                    }
                }

                float pa[2][2][4];
                #pragma unroll
                for (int nt = 0; nt < 2; ++nt)
                    #pragma unroll
                    for (int cp = 0; cp < 2; ++cp) {
                        pa[nt][cp][0]=0.f; pa[nt][cp][1]=0.f; pa[nt][cp][2]=0.f; pa[nt][cp][3]=0.f;
                    }
                const float4* uj = (const float4*)u4f + (rr*2 + jh)*Nn;
                #pragma unroll
                for (int mt = 0; mt < 4; ++mt) {
                    #pragma unroll
                    for (int rg = 0; rg < 2; ++rg) {
                        int i = mt*16 + r4 + rg*8;
                        float4 uv = uj[i];
                        float2 h0 = hreg[mt][rg][0];
                        float2 h1 = hreg[mt][rg][1];
                        #pragma unroll
                        for (int cp = 0; cp < 2; ++cp) {
                            float m0 = acc[mt][0][rg*2+cp] * (cp ? h0.y : h0.x);
                            pa[0][cp][0] += m0;
                            pa[0][cp][1] = fmaf(m0, uv.x, pa[0][cp][1]);
                            pa[0][cp][2] = fmaf(m0, uv.y, pa[0][cp][2]);
                            pa[0][cp][3] = fmaf(m0, uv.z, pa[0][cp][3]);
                            float m1 = acc[mt][1][rg*2+cp] * (cp ? h1.y : h1.x);
                            pa[1][cp][0] += m1;
                            pa[1][cp][1] = fmaf(m1, uv.x, pa[1][cp][1]);
                            pa[1][cp][2] = fmaf(m1, uv.y, pa[1][cp][2]);
                            pa[1][cp][3] = fmaf(m1, uv.z, pa[1][cp][3]);
                        }
                    }
                }
                #pragma unroll
                for (int nt = 0; nt < 2; ++nt)
                    #pragma unroll
                    for (int cp = 0; cp < 2; ++cp)
                        #pragma unroll
                        for (int q = 0; q < 4; ++q) {
                            float v = pa[nt][cp][q];
                            v += __shfl_xor_sync(0xffffffffu, v, 4);
                            v += __shfl_xor_sync(0xffffffffu, v, 8);
                            v += __shfl_xor_sync(0xffffffffu, v, 16);
                            pa[nt][cp][q] = v;
                        }
                if (lane < 4) {
                    uint32_t* aF = g_aF + (b*16 + jg)*1024 + widh*128 + lane*2;
                    const int node = rr*2 + jh;
                    #pragma unroll
                    for (int nt = 0; nt < 2; ++nt)
                        #pragma unroll
                        for (int q = 0; q < 4; ++q)
                            aF[(q*4 + node)*8 + nt] =
                                pack_h2(pa[nt][0][q]*s63, pa[nt][1][q]*s63);
                }
            }
            __syncthreads();
        }

        // ---- fused update for own 4 nodes ----
        {
            const uint32_t* aB  = g_aF + (b*16 + jg)*1024 + r4*8 + q4*2;
            const uint32_t* WuB = g_WuH + layer*8192 + (widh*16 + r4)*8 + q4*2;
            const uint32_t* WmB = g_WmH + layer*8192 + (widh*16 + r4)*8 + q4*2;
            float aU0[4] = {0.f,0.f,0.f,0.f}, aU1[4] = {0.f,0.f,0.f,0.f};
            float aM0[4] = {0.f,0.f,0.f,0.f}, aM1[4] = {0.f,0.f,0.f,0.f};
            #pragma unroll
            for (int kb = 0; kb < 8; ++kb) {
                uint2 A0 = *(const uint2*)(aB + kb*128);
                uint2 A1 = *(const uint2*)(aB + kb*128 + 64);
                uint2 Bu0 = *(const uint2*)(WuB + kb*1024);
                uint2 Bu1 = *(const uint2*)(WuB + kb*1024 + 64);
                uint2 Bm0 = *(const uint2*)(WmB + kb*1024);
                uint2 Bm1 = *(const uint2*)(WmB + kb*1024 + 64);
                mma_f16(aU0, A0.x, A1.x, A0.y, A1.y, Bu0.x, Bu0.y);
                mma_f16(aU1, A0.x, A1.x, A0.y, A1.y, Bu1.x, Bu1.y);
                mma_f16(aM0, A0.x, A1.x, A0.y, A1.y, Bm0.x, Bm0.y);
                mma_f16(aM1, A0.x, A1.x, A0.y, A1.y, Bm1.x, Bm1.y);
            }
            const int c0 = widh*16 + q4*2;
            if (r4 < 4) {
                const size_t n = (size_t)(b*Nn + jg*4 + r4);
                float2 hv0 = *(const float2*)(h_in + n*Hh + c0);
                float2 hv1 = *(const float2*)(h_in + n*Hh + c0 + 8);
                hv0.x += aU0[0]; hv0.y += aU0[1];
                hv1.x += aU1[0]; hv1.y += aU1[1];
                *(float2*)(h_out + n*Hh + c0)     = hv0;
                *(float2*)(h_out + n*Hh + c0 + 8) = hv1;
            }
            if (r4 >= 4) {
                const size_t n = (size_t)(b*Nn + jg*4 + (r4 - 4));
                float* vd = v_out + (n*3 + 0)*Hh + c0;
                const float* vs = v_in + (n*3 + 0)*Hh + c0;
                float2 v0 = *(const float2*)(vs);
                float2 v1 = *(const float2*)(vs + 8);
                v0.x += aM0[0]; v0.y += aM0[1];
                v1.x += aM1[0]; v1.y += aM1[1];
                *(float2*)(vd)     = v0;
                *(float2*)(vd + 8) = v1;
            }
            {
                const int d    = (r4 < 4) ? 1 : 2;
                const int node = (r4 < 4) ? r4 : (r4 - 4);
                const size_t n = (size_t)(b*Nn + jg*4 + node);
                float* vd = v_out + (n*3 + d)*Hh + c0;
                const float* vs = v_in + (n*3 + d)*Hh + c0;
                float2 v0 = *(const float2*)(vs);
                float2 v1 = *(const float2*)(vs + 8);
                v0.x += aM0[2]; v0.y += aM0[3];
                v1.x += aM1[2]; v1.y += aM1[3];
                *(float2*)(vd)     = v0;
                *(float2*)(vd + 8) = v1;
            }
        }
    }
}

// ---------------- K4: tensorized gated readout (16 nodes/CTA) -------------
__global__ __launch_bounds__(256, 4)
void readout_kernel(const float* __restrict__ fsp,
                    float* __restrict__ out) {
    __shared__ uint32_t rsm[4096];           // [0:2048) h A-frags, [2048:4096) t A-frags
    __shared__ float red[8][48];

    const int n0  = blockIdx.x * 16;
    const int tid = threadIdx.x;
    const int lane = tid & 31;
    const int widh = tid >> 5;
    const int r4 = lane >> 2, q4 = lane & 3;

    for (int idx = tid; idx < 2048; idx += 256) {
        int w  = idx & 7;
        int r  = (idx >> 3) & 15;
        int kb = idx >> 7;
        int k  = kb*16 + ((w >> 1) & 3)*2 + (w & 1)*8;
        float2 v = *(const float2*)(g_h + (size_t)(n0 + r)*Hh + k);
        rsm[idx] = pack_h2(v.x, v.y);
    }
    __syncthreads();

    float a0[4] = {0.f,0.f,0.f,0.f}, a1[4] = {0.f,0.f,0.f,0.f};
    {
        const uint32_t* Ap = rsm + r4*8 + q4*2;
        const uint32_t* Bp = g_Wg1H + (widh*16 + r4)*8 + q4*2;
        #pragma unroll
        for (int kb = 0; kb < 8; ++kb) {
            uint2 A0 = *(const uint2*)(Ap + kb*128);
            uint2 A1 = *(const uint2*)(Ap + kb*128 + 64);
            uint2 B0 = *(const uint2*)(Bp + kb*1024);
            uint2 B1 = *(const uint2*)(Bp + kb*1024 + 64);
            mma_f16(a0, A0.x, A1.x, A0.y, A1.y, B0.x, B0.y);
            mma_f16(a1, A0.x, A1.x, A0.y, A1.y, B1.x, B1.y);
        }
    }
    {
        uint32_t* Tb = rsm + 2048 + widh*128 + r4*8 + q4*2;
        Tb[0]  = pack_h2(silu_f(a0[0]), silu_f(a0[1]));
        Tb[1]  = pack_h2(silu_f(a1[0]), silu_f(a1[1]));
        Tb[64] = pack_h2(silu_f(a0[2]), silu_f(a0[3]));
        Tb[65] = pack_h2(silu_f(a1[2]), silu_f(a1[3]));
    }
    __syncthreads();

    float g0[4] = {0.f,0.f,0.f,0.f}, g1[4] = {0.f,0.f,0.f,0.f};
    {
        const uint32_t* Ap = rsm + 2048 + r4*8 + q4*2;
        const uint32_t* Bp = g_Wg2H + (widh*16 + r4)*8 + q4*2;
        #pragma unroll
        for (int kb = 0; kb < 8; ++kb) {
            uint2 A0 = *(const uint2*)(Ap + kb*128);
            uint2 A1 = *(const uint2*)(Ap + kb*128 + 64);
            uint2 B0 = *(const uint2*)(Bp + kb*1024);
            uint2 B1 = *(const uint2*)(Bp + kb*1024 + 64);
            mma_f16(g0, A0.x, A1.x, A0.y, A1.y, B0.x, B0.y);
            mma_f16(g1, A0.x, A1.x, A0.y, A1.y, B1.x, B1.y);
        }
    }

    float pr[2][3];
    #pragma unroll
    for (int rg = 0; rg < 2; ++rg) { pr[rg][0]=0.f; pr[rg][1]=0.f; pr[rg][2]=0.f; }
    #pragma unroll
    for (int rg = 0; rg < 2; ++rg) {
        const size_t n = (size_t)(n0 + r4 + rg*8);
        #pragma unroll
        for (int nt = 0; nt < 2; ++nt) {
            const int c = widh*16 + nt*8 + q4*2;
            float gv0 = (nt ? g1 : g0)[rg*2 + 0];
            float gv1 = (nt ? g1 : g0)[rg*2 + 1];
            #pragma unroll
            for (int d = 0; d < 3; ++d) {
                float2 vv = *(const float2*)(g_v + (n*3 + d)*Hh + c);
                pr[rg][d] = fmaf(vv.x, gv0, fmaf(vv.y, gv1, pr[rg][d]));
            }
        }
    }
    #pragma unroll
    for (int rg = 0; rg < 2; ++rg)
        #pragma unroll
        for (int d = 0; d < 3; ++d) {
            float v = pr[rg][d];
            v += __shfl_xor_sync(0xffffffffu, v, 1);
            v += __shfl_xor_sync(0xffffffffu, v, 2);
            pr[rg][d] = v;
        }
    if (q4 == 0) {
        #pragma unroll
        for (int rg = 0; rg < 2; ++rg)
            #pragma unroll
            for (int d = 0; d < 3; ++d)
                red[widh][(r4 + rg*8)*3 + d] = pr[rg][d];
    }
    __syncthreads();
    if (tid < 48) {
        float s = 0.f;
        #pragma unroll
        for (int w = 0; w < 8; ++w) s += red[w][tid];
        out[(n0 + tid/3)*3 + (tid % 3)] = s * fsp[0];
    }
}

// ---------------- launch ---------------------------------------------------
extern "C" void kernel_launch(void* const* d_in, const int* in_sizes, int n_in,
                              void* d_out, int out_size) {
    const float* positions = (const float*)d_in[0];
    const int*   nodef     = (const int*)  d_in[1];
    const float* gf        = (const float*)d_in[2];
    const float* emb       = (const float*)d_in[3];
    const float* Wt        = (const float*)d_in[4];
    const float* Wr1       = (const float*)d_in[5];
    const float* Wr2       = (const float*)d_in[6];
    const float* Wupd      = (const float*)d_in[7];
    const float* Wmix      = (const float*)d_in[8];
    const float* Wg1       = (const float*)d_in[9];
    const float* Wg2       = (const float*)d_in[10];
    const float* fs        = (const float*)d_in[11];
    float*       out       = (float*)d_out;

    const int msg_smem = MSG_WORDS * 4;
    cudaFuncSetAttribute(msg_kernel, cudaFuncAttributeMaxDynamicSharedMemorySize, msg_smem);

    setup_kernel<<<512 + 3*Ll + 2, 256>>>(nodef, gf, emb, Wt, Wr2, Wupd, Wmix, Wg1, Wg2);

    for (int l = 0; l < Ll; ++l) {
        msg_kernel<<<MSG_GRID, 256, msg_smem>>>(positions, Wr1 + l*NBb*Hh, l);
    }
    readout_kernel<<<Bb*Nn/16, 256>>>(fs, out);
}